// round 1
// baseline (speedup 1.0000x reference)
#include <cuda_runtime.h>
#include <cstdint>

// ---------------------------------------------------------------------------
// Conversation_Self_Attention: B=64, S=512, D=DK=DV=512
//   Qc = [ (sent@Wq^T+bq)*norm | (pos@Wpq^T+bpq)*norm ]   [B*S, 1024]
//   Kc = [ (sent@Wk^T+bk)      | (pos@Wpk^T+bpk)      ]   [B*S, 1024]
//   V  =   (sent@Wv^T+bv)                                  [B*S, 512]
//   scores[b] = Qc_b @ Kc_b^T + bias   (norm folded into Qc)
//   att = softmax(scores, last axis)  -> d_out[0 : B*S*S]
//   out[b] = att_b @ V_b^T            -> d_out[B*S*S : 2*B*S*S]
// All GEMMs: NT, tf32 mma.sync (m16n8k8), fp32 accumulate.
// ---------------------------------------------------------------------------

#define BM 128
#define BN 128
#define BK 32
#define PAD 4
#define BKP (BK + PAD)      // 36 -> conflict-free fragment loads
#define THREADS 256
#define SMEM_BYTES (2 * (BM * BKP + BN * BKP) * 4)  // 73728

static const int Bv = 64, Sv = 512, Dv = 512;

// scratch (static device arrays: allocation-free contract)
__device__ float g_Qc[64L * 512 * 1024];
__device__ float g_Kc[64L * 512 * 1024];
__device__ float g_V [64L * 512 * 512];
__device__ float g_S [64L * 512 * 512];

__device__ __forceinline__ unsigned cvt_tf32(float x) {
    unsigned r;
    asm("cvt.rna.tf32.f32 %0, %1;" : "=r"(r) : "f"(x));
    return r;
}

// C[z][m,n] = (sum_k A[z][m,k]*B[z][n,k] + bias[n]) * alpha
__global__ void gemm_nt_tf32(const float* __restrict__ A, int lda, long Astride,
                             const float* __restrict__ B, int ldb, long Bstride,
                             const float* __restrict__ bias, float alpha,
                             float* __restrict__ C, int ldc, long Cstride,
                             int K)
{
    extern __shared__ float smem[];
    float* sA = smem;                     // [2][BM][BKP]
    float* sB = smem + 2 * BM * BKP;      // [2][BN][BKP]

    const int tid  = threadIdx.x;
    const int lane = tid & 31;
    const int warp = tid >> 5;
    const int wm   = warp & 1;            // 2 warps in M  -> 64 rows/warp
    const int wn   = warp >> 1;           // 4 warps in N  -> 32 cols/warp

    const int bm = blockIdx.x * BM;
    const int bn = blockIdx.y * BN;
    const int z  = blockIdx.z;

    const float* Ab = A + (long)z * Astride;
    const float* Bb = B + (long)z * Bstride;
    float*       Cb = C + (long)z * Cstride;

    const int lrow = tid >> 3;            // 0..31
    const int lcol = (tid & 7) * 4;       // 0,4,...,28

    float acc[4][4][4];
    #pragma unroll
    for (int i = 0; i < 4; i++)
        #pragma unroll
        for (int j = 0; j < 4; j++)
            #pragma unroll
            for (int k = 0; k < 4; k++) acc[i][j][k] = 0.f;

    auto load_tile = [&](int kt, int buf) {
        const int k0 = kt * BK;
        float* dA = sA + buf * BM * BKP;
        float* dB = sB + buf * BN * BKP;
        #pragma unroll
        for (int r = 0; r < 4; r++) {
            const int row = lrow + r * 32;
            const float* gA = Ab + (long)(bm + row) * lda + k0 + lcol;
            unsigned sa = (unsigned)__cvta_generic_to_shared(dA + row * BKP + lcol);
            asm volatile("cp.async.ca.shared.global [%0], [%1], 16;\n" :: "r"(sa), "l"(gA));
            const float* gB = Bb + (long)(bn + row) * ldb + k0 + lcol;
            unsigned sb = (unsigned)__cvta_generic_to_shared(dB + row * BKP + lcol);
            asm volatile("cp.async.ca.shared.global [%0], [%1], 16;\n" :: "r"(sb), "l"(gB));
        }
        asm volatile("cp.async.commit_group;\n");
    };

    const int KT = K / BK;
    load_tile(0, 0);

    for (int kt = 0; kt < KT; kt++) {
        const int buf = kt & 1;
        if (kt + 1 < KT) {
            load_tile(kt + 1, buf ^ 1);
            asm volatile("cp.async.wait_group 1;\n");
        } else {
            asm volatile("cp.async.wait_group 0;\n");
        }
        __syncthreads();

        const float* tA = sA + buf * BM * BKP;
        const float* tB = sB + buf * BN * BKP;

        #pragma unroll
        for (int kk = 0; kk < 4; kk++) {
            unsigned a[4][4], b[4][2];
            const int arow = wm * 64 + (lane >> 2);
            const int acol = kk * 8 + (lane & 3);
            #pragma unroll
            for (int mt = 0; mt < 4; mt++) {
                const int r = arow + mt * 16;
                a[mt][0] = cvt_tf32(tA[(r    ) * BKP + acol    ]);
                a[mt][1] = cvt_tf32(tA[(r + 8) * BKP + acol    ]);
                a[mt][2] = cvt_tf32(tA[(r    ) * BKP + acol + 4]);
                a[mt][3] = cvt_tf32(tA[(r + 8) * BKP + acol + 4]);
            }
            const int bcol = wn * 32 + (lane >> 2);
            const int brow = kk * 8 + (lane & 3);
            #pragma unroll
            for (int nt = 0; nt < 4; nt++) {
                const int c = bcol + nt * 8;
                b[nt][0] = cvt_tf32(tB[c * BKP + brow    ]);
                b[nt][1] = cvt_tf32(tB[c * BKP + brow + 4]);
            }
            #pragma unroll
            for (int mt = 0; mt < 4; mt++)
                #pragma unroll
                for (int nt = 0; nt < 4; nt++) {
                    float* d = acc[mt][nt];
                    asm volatile(
                        "mma.sync.aligned.m16n8k8.row.col.f32.tf32.tf32.f32 "
                        "{%0,%1,%2,%3}, {%4,%5,%6,%7}, {%8,%9}, {%0,%1,%2,%3};\n"
                        : "+f"(d[0]), "+f"(d[1]), "+f"(d[2]), "+f"(d[3])
                        : "r"(a[mt][0]), "r"(a[mt][1]), "r"(a[mt][2]), "r"(a[mt][3]),
                          "r"(b[nt][0]), "r"(b[nt][1]));
                }
        }
        __syncthreads();
    }

    #pragma unroll
    for (int mt = 0; mt < 4; mt++) {
        const int row = bm + wm * 64 + mt * 16 + (lane >> 2);
        #pragma unroll
        for (int nt = 0; nt < 4; nt++) {
            const int col = bn + wn * 32 + nt * 8 + (lane & 3) * 2;
            const float b0 = bias ? bias[col]     : 0.f;
            const float b1 = bias ? bias[col + 1] : 0.f;
            const float* d = acc[mt][nt];
            Cb[(long)(row    ) * ldc + col    ] = (d[0] + b0) * alpha;
            Cb[(long)(row    ) * ldc + col + 1] = (d[1] + b1) * alpha;
            Cb[(long)(row + 8) * ldc + col    ] = (d[2] + b0) * alpha;
            Cb[(long)(row + 8) * ldc + col + 1] = (d[3] + b1) * alpha;
        }
    }
}

// row-wise softmax over 512 elements; one block (128 threads) per row
__global__ void softmax512(const float* __restrict__ S, float* __restrict__ O)
{
    const long row = blockIdx.x;
    const float4 v = ((const float4*)(S + row * 512))[threadIdx.x];
    const int tid = threadIdx.x;

    float m = fmaxf(fmaxf(v.x, v.y), fmaxf(v.z, v.w));
    #pragma unroll
    for (int off = 16; off; off >>= 1) m = fmaxf(m, __shfl_xor_sync(~0u, m, off));
    __shared__ float redm[4];
    if ((tid & 31) == 0) redm[tid >> 5] = m;
    __syncthreads();
    m = fmaxf(fmaxf(redm[0], redm[1]), fmaxf(redm[2], redm[3]));

    const float e0 = __expf(v.x - m), e1 = __expf(v.y - m);
    const float e2 = __expf(v.z - m), e3 = __expf(v.w - m);
    float s = e0 + e1 + e2 + e3;
    #pragma unroll
    for (int off = 16; off; off >>= 1) s += __shfl_xor_sync(~0u, s, off);
    __shared__ float reds[4];
    if ((tid & 31) == 0) reds[tid >> 5] = s;
    __syncthreads();
    s = reds[0] + reds[1] + reds[2] + reds[3];

    const float inv = 1.0f / s;
    ((float4*)(O + row * 512))[tid] = make_float4(e0 * inv, e1 * inv, e2 * inv, e3 * inv);
}

extern "C" void kernel_launch(void* const* d_in, const int* in_sizes, int n_in,
                              void* d_out, int out_size)
{
    const float* sent = (const float*)d_in[0];
    const float* pos  = (const float*)d_in[1];
    // d_in[2] = branch_emb: unused by the reference
    const float* Wq   = (const float*)d_in[3];
    const float* bq   = (const float*)d_in[4];
    const float* Wk   = (const float*)d_in[5];
    const float* bk   = (const float*)d_in[6];
    const float* Wv   = (const float*)d_in[7];
    const float* bv   = (const float*)d_in[8];
    const float* Wpq  = (const float*)d_in[9];
    const float* bpq  = (const float*)d_in[10];
    const float* Wpk  = (const float*)d_in[11];
    const float* bpk  = (const float*)d_in[12];
    const float* bias = (const float*)d_in[13];
    float* out = (float*)d_out;

    float *Qc, *Kc, *V, *Sc;
    cudaGetSymbolAddress((void**)&Qc, g_Qc);
    cudaGetSymbolAddress((void**)&Kc, g_Kc);
    cudaGetSymbolAddress((void**)&V,  g_V);
    cudaGetSymbolAddress((void**)&Sc, g_S);

    cudaFuncSetAttribute(gemm_nt_tf32, cudaFuncAttributeMaxDynamicSharedMemorySize, SMEM_BYTES);

    const float norm = 0.03125f;  // 1/sqrt(2*512)
    const long  M    = (long)Bv * Sv;          // 32768
    const long  rowQK = 512L * 1024;           // per-batch stride in Qc/Kc
    const long  rowSS = 512L * 512;            // per-batch stride in scores/V/out

    // Stage 1: projections (M=32768, N=512, K=512)
    dim3 g1(M / BM, Dv / BN, 1);
    gemm_nt_tf32<<<g1, THREADS, SMEM_BYTES>>>(sent, 512, 0, Wq,  512, 0, bq,  norm, Qc,        1024, 0, 512);
    gemm_nt_tf32<<<g1, THREADS, SMEM_BYTES>>>(pos,  512, 0, Wpq, 512, 0, bpq, norm, Qc + 512,  1024, 0, 512);
    gemm_nt_tf32<<<g1, THREADS, SMEM_BYTES>>>(sent, 512, 0, Wk,  512, 0, bk,  1.f,  Kc,        1024, 0, 512);
    gemm_nt_tf32<<<g1, THREADS, SMEM_BYTES>>>(pos,  512, 0, Wpk, 512, 0, bpk, 1.f,  Kc + 512,  1024, 0, 512);
    gemm_nt_tf32<<<g1, THREADS, SMEM_BYTES>>>(sent, 512, 0, Wv,  512, 0, bv,  1.f,  V,          512, 0, 512);

    // Stage 2: fused text+pos scores per batch (K=1024), + bias epilogue
    dim3 g2(Sv / BM, Sv / BN, Bv);
    gemm_nt_tf32<<<g2, THREADS, SMEM_BYTES>>>(Qc, 1024, rowQK, Kc, 1024, rowQK, bias, 1.f, Sc, 512, rowSS, 1024);

    // Stage 3: softmax rows -> first half of d_out (att_softmax)
    softmax512<<<(unsigned)M, 128>>>(Sc, out);

    // Stage 4: output[b] = att_b @ V_b^T -> second half of d_out
    gemm_nt_tf32<<<g2, THREADS, SMEM_BYTES>>>(out, 512, rowSS, V, 512, rowSS, nullptr, 1.f,
                                              out + (long)Bv * rowSS, 512, rowSS, 512);
}

// round 3
// speedup vs baseline: 1.0560x; 1.0560x over previous
#include <cuda_runtime.h>
#include <cstdint>

// ---------------------------------------------------------------------------
// Conversation_Self_Attention: B=64, S=512, D=DK=DV=512  (sm_103 mma.sync path;
// tcgen05 is unavailable: bench PTX stage targets plain sm_103)
//
//   pre-round all GEMM operands to tf32 (rna) once -> no in-kernel cvt
//   Qc = [ (sent@Wq^T+bq)*2^-5 | (pos@Wpq^T+bpq)*2^-5 ]  rna  [B*S,1024]
//   Kc = [ sent@Wk^T+bk        | pos@Wpk^T+bpk        ]  rna  [B*S,1024]
//   V  =   sent@Wv^T+bv                                  rna  [B*S,512]
//   scores[b] = Qc_b @ Kc_b^T + bias        (full fp32)
//   att = softmax(scores) -> d_out[0:B*S*S] (full) + rna copy in scratch
//   out[b] = att_b @ V_b^T -> d_out[B*S*S:]
//
// GEMM: NT, tf32 mma.sync m16n8k8, fp32 accum. 128x128 block, 4 warps,
// 64x64 warp tile (1.0 LDS.32 per MMA), cp.async double buffer.
// ---------------------------------------------------------------------------

#define BM 128
#define BN 128
#define BK 32
#define BKP 36                                // pad -> conflict-free LDS
#define THREADS 128
#define SMEM_BYTES (2 * (BM + BN) * BKP * 4)  // 73728

static const int Bv = 64, Sv = 512;

// scratch (static device arrays: allocation-free contract)
__device__ float g_Ar[64L * 512 * 512];     // rna(sent)
__device__ float g_Pr[64L * 512 * 512];     // rna(pos)
__device__ float g_Wr[5L * 512 * 512];      // rna(Wq,Wk,Wv,Wpq,Wpk)
__device__ float g_Qc[64L * 512 * 1024];
__device__ float g_Kc[64L * 512 * 1024];
__device__ float g_V [64L * 512 * 512];
__device__ float g_S [64L * 512 * 512];     // scores, then rna(att)

__device__ __forceinline__ float tf32r(float x) {
    unsigned u;
    asm("cvt.rna.tf32.f32 %0, %1;" : "=r"(u) : "f"(x));
    return __uint_as_float(u);
}

// C[z][m,n] = (sum_k A[z][m,k]*B[z][n,k] + bias[n]) * alpha   [optionally rna]
__global__ void __launch_bounds__(THREADS, 2)
gemm_nt_tf32(const float* __restrict__ A, int lda, long As,
             const float* __restrict__ B, int ldb, long Bs,
             const float* __restrict__ bias, float alpha,
             float* __restrict__ C, int ldc, long Cs,
             int K, int rnd)
{
    extern __shared__ float smem[];
    float* sA = smem;                     // [2][BM][BKP]
    float* sB = smem + 2 * BM * BKP;      // [2][BN][BKP]

    const int tid  = threadIdx.x;
    const int lane = tid & 31;
    const int warp = tid >> 5;
    const int wm   = warp & 1;            // 2 warps in M -> 64 rows/warp
    const int wn   = warp >> 1;           // 2 warps in N -> 64 cols/warp

    const int bm = blockIdx.x * BM;
    const int bn = blockIdx.y * BN;
    const int z  = blockIdx.z;

    const float* Ab = A + (size_t)z * As;
    const float* Bb = B + (size_t)z * Bs;
    float*       Cb = C + (size_t)z * Cs;

    const int lrow = tid >> 3;            // 0..15
    const int lcol = (tid & 7) * 4;       // 16B granule within 128B row

    float acc[4][8][4];
    #pragma unroll
    for (int i = 0; i < 4; i++)
        #pragma unroll
        for (int j = 0; j < 8; j++)
            #pragma unroll
            for (int k = 0; k < 4; k++) acc[i][j][k] = 0.f;

    auto load_tile = [&](int kt, int buf) {
        const int k0 = kt * BK;
        float* dA = sA + buf * BM * BKP;
        float* dB = sB + buf * BN * BKP;
        #pragma unroll
        for (int r = 0; r < 8; r++) {
            const int row = lrow + r * 16;
            {
                const float* g = Ab + (size_t)(bm + row) * lda + k0 + lcol;
                unsigned s = (unsigned)__cvta_generic_to_shared(dA + row * BKP + lcol);
                asm volatile("cp.async.cg.shared.global [%0], [%1], 16;\n" :: "r"(s), "l"(g));
            }
            {
                const float* g = Bb + (size_t)(bn + row) * ldb + k0 + lcol;
                unsigned s = (unsigned)__cvta_generic_to_shared(dB + row * BKP + lcol);
                asm volatile("cp.async.cg.shared.global [%0], [%1], 16;\n" :: "r"(s), "l"(g));
            }
        }
        asm volatile("cp.async.commit_group;\n");
    };

    const int KT = K / BK;
    load_tile(0, 0);

    for (int kt = 0; kt < KT; kt++) {
        const int buf = kt & 1;
        if (kt + 1 < KT) {
            load_tile(kt + 1, buf ^ 1);
            asm volatile("cp.async.wait_group 1;\n");
        } else {
            asm volatile("cp.async.wait_group 0;\n");
        }
        __syncthreads();

        const float* tA = sA + buf * BM * BKP;
        const float* tB = sB + buf * BN * BKP;

        #pragma unroll
        for (int kk = 0; kk < 4; kk++) {
            unsigned a[4][4], b[8][2];
            const int arow = wm * 64 + (lane >> 2);
            const int acol = kk * 8 + (lane & 3);
            #pragma unroll
            for (int mt = 0; mt < 4; mt++) {
                const int r = arow + mt * 16;
                a[mt][0] = __float_as_uint(tA[(r    ) * BKP + acol    ]);
                a[mt][1] = __float_as_uint(tA[(r + 8) * BKP + acol    ]);
                a[mt][2] = __float_as_uint(tA[(r    ) * BKP + acol + 4]);
                a[mt][3] = __float_as_uint(tA[(r + 8) * BKP + acol + 4]);
            }
            const int bcol = wn * 64 + (lane >> 2);
            const int brow = kk * 8 + (lane & 3);
            #pragma unroll
            for (int nt = 0; nt < 8; nt++) {
                const int c = bcol + nt * 8;
                b[nt][0] = __float_as_uint(tB[c * BKP + brow    ]);
                b[nt][1] = __float_as_uint(tB[c * BKP + brow + 4]);
            }
            #pragma unroll
            for (int mt = 0; mt < 4; mt++)
                #pragma unroll
                for (int nt = 0; nt < 8; nt++) {
                    float* d = acc[mt][nt];
                    asm volatile(
                        "mma.sync.aligned.m16n8k8.row.col.f32.tf32.tf32.f32 "
                        "{%0,%1,%2,%3}, {%4,%5,%6,%7}, {%8,%9}, {%0,%1,%2,%3};\n"
                        : "+f"(d[0]), "+f"(d[1]), "+f"(d[2]), "+f"(d[3])
                        : "r"(a[mt][0]), "r"(a[mt][1]), "r"(a[mt][2]), "r"(a[mt][3]),
                          "r"(b[nt][0]), "r"(b[nt][1]));
                }
        }
        __syncthreads();
    }

    #pragma unroll
    for (int mt = 0; mt < 4; mt++) {
        const int row = bm + wm * 64 + mt * 16 + (lane >> 2);
        #pragma unroll
        for (int nt = 0; nt < 8; nt++) {
            const int col = bn + wn * 64 + nt * 8 + (lane & 3) * 2;
            float b0 = 0.f, b1 = 0.f;
            if (bias) { b0 = bias[col]; b1 = bias[col + 1]; }
            const float* d = acc[mt][nt];
            float v0 = (d[0] + b0) * alpha;
            float v1 = (d[1] + b1) * alpha;
            float v2 = (d[2] + b0) * alpha;
            float v3 = (d[3] + b1) * alpha;
            if (rnd) { v0 = tf32r(v0); v1 = tf32r(v1); v2 = tf32r(v2); v3 = tf32r(v3); }
            *reinterpret_cast<float2*>(Cb + (size_t)(row    ) * ldc + col) = make_float2(v0, v1);
            *reinterpret_cast<float2*>(Cb + (size_t)(row + 8) * ldc + col) = make_float2(v2, v3);
        }
    }
}

// ---------------- elementwise rna(tf32) copy ----------------
__global__ void round_copy(const float* __restrict__ x, float* __restrict__ y, long n)
{
    long i = ((long)blockIdx.x * blockDim.x + threadIdx.x) * 4;
    if (i >= n) return;
    float4 v = *reinterpret_cast<const float4*>(x + i);
    v.x = tf32r(v.x); v.y = tf32r(v.y); v.z = tf32r(v.z); v.w = tf32r(v.w);
    *reinterpret_cast<float4*>(y + i) = v;
}

// ---------------- softmax over 512, dual output (full + rna) ----------------
__global__ void softmax512(const float* __restrict__ S,
                           float* __restrict__ Ofull,
                           float* __restrict__ Ornd)
{
    const long row = blockIdx.x;
    const int tid = threadIdx.x;
    const float4 v = ((const float4*)(S + row * 512))[tid];

    float m = fmaxf(fmaxf(v.x, v.y), fmaxf(v.z, v.w));
    #pragma unroll
    for (int off = 16; off; off >>= 1) m = fmaxf(m, __shfl_xor_sync(~0u, m, off));
    __shared__ float redm[4];
    if ((tid & 31) == 0) redm[tid >> 5] = m;
    __syncthreads();
    m = fmaxf(fmaxf(redm[0], redm[1]), fmaxf(redm[2], redm[3]));

    const float e0 = __expf(v.x - m), e1 = __expf(v.y - m);
    const float e2 = __expf(v.z - m), e3 = __expf(v.w - m);
    float s = e0 + e1 + e2 + e3;
    #pragma unroll
    for (int off = 16; off; off >>= 1) s += __shfl_xor_sync(~0u, s, off);
    __shared__ float reds[4];
    if ((tid & 31) == 0) reds[tid >> 5] = s;
    __syncthreads();
    s = reds[0] + reds[1] + reds[2] + reds[3];

    const float inv = 1.0f / s;
    const float p0 = e0 * inv, p1 = e1 * inv, p2 = e2 * inv, p3 = e3 * inv;
    ((float4*)(Ofull + row * 512))[tid] = make_float4(p0, p1, p2, p3);
    ((float4*)(Ornd  + row * 512))[tid] = make_float4(tf32r(p0), tf32r(p1), tf32r(p2), tf32r(p3));
}

// ---------------- launcher ----------------
extern "C" void kernel_launch(void* const* d_in, const int* in_sizes, int n_in,
                              void* d_out, int out_size)
{
    const float* sent = (const float*)d_in[0];
    const float* pos  = (const float*)d_in[1];
    // d_in[2] = branch_emb: unused by the reference
    const float* Wq   = (const float*)d_in[3];
    const float* bq   = (const float*)d_in[4];
    const float* Wk   = (const float*)d_in[5];
    const float* bk   = (const float*)d_in[6];
    const float* Wv   = (const float*)d_in[7];
    const float* bv   = (const float*)d_in[8];
    const float* Wpq  = (const float*)d_in[9];
    const float* bpq  = (const float*)d_in[10];
    const float* Wpk  = (const float*)d_in[11];
    const float* bpk  = (const float*)d_in[12];
    const float* bias = (const float*)d_in[13];
    float* out = (float*)d_out;

    float *Ar, *Pr, *Wr, *Qc, *Kc, *V, *Sc;
    cudaGetSymbolAddress((void**)&Ar, g_Ar);
    cudaGetSymbolAddress((void**)&Pr, g_Pr);
    cudaGetSymbolAddress((void**)&Wr, g_Wr);
    cudaGetSymbolAddress((void**)&Qc, g_Qc);
    cudaGetSymbolAddress((void**)&Kc, g_Kc);
    cudaGetSymbolAddress((void**)&V,  g_V);
    cudaGetSymbolAddress((void**)&Sc, g_S);

    cudaFuncSetAttribute(gemm_nt_tf32, cudaFuncAttributeMaxDynamicSharedMemorySize, SMEM_BYTES);

    const long nEmb = (long)Bv * Sv * 512;      // 16,777,216
    const long nW   = 512L * 512;               // 262,144
    const float norm = 0.03125f;                // 1/sqrt(2*512), exact power of 2
    const long  M     = (long)Bv * Sv;          // 32768
    const long  rowQK = 512L * 1024;
    const long  rowSS = 512L * 512;

    // Stage 0: pre-round all tf32 operands (mma.sync consumes raw bits)
    round_copy<<<(unsigned)(nEmb / 2048), 512>>>(sent, Ar, nEmb);
    round_copy<<<(unsigned)(nEmb / 2048), 512>>>(pos,  Pr, nEmb);
    round_copy<<<(unsigned)(nW / 2048), 512>>>(Wq,  Wr + 0 * nW, nW);
    round_copy<<<(unsigned)(nW / 2048), 512>>>(Wk,  Wr + 1 * nW, nW);
    round_copy<<<(unsigned)(nW / 2048), 512>>>(Wv,  Wr + 2 * nW, nW);
    round_copy<<<(unsigned)(nW / 2048), 512>>>(Wpq, Wr + 3 * nW, nW);
    round_copy<<<(unsigned)(nW / 2048), 512>>>(Wpk, Wr + 4 * nW, nW);

    // Stage 1: projections (M=32768, N=512, K=512), rna-rounded outputs
    dim3 g1((unsigned)(M / BM), 512 / BN, 1);
    gemm_nt_tf32<<<g1, THREADS, SMEM_BYTES>>>(Ar, 512, 0, Wr + 0 * nW, 512, 0, bq,  norm, Qc,       1024, 0, 512, 1);
    gemm_nt_tf32<<<g1, THREADS, SMEM_BYTES>>>(Pr, 512, 0, Wr + 3 * nW, 512, 0, bpq, norm, Qc + 512, 1024, 0, 512, 1);
    gemm_nt_tf32<<<g1, THREADS, SMEM_BYTES>>>(Ar, 512, 0, Wr + 1 * nW, 512, 0, bk,  1.f,  Kc,       1024, 0, 512, 1);
    gemm_nt_tf32<<<g1, THREADS, SMEM_BYTES>>>(Pr, 512, 0, Wr + 4 * nW, 512, 0, bpk, 1.f,  Kc + 512, 1024, 0, 512, 1);
    gemm_nt_tf32<<<g1, THREADS, SMEM_BYTES>>>(Ar, 512, 0, Wr + 2 * nW, 512, 0, bv,  1.f,  V,         512, 0, 512, 1);

    // Stage 2: fused text+pos scores per batch (K=1024) + bias, full fp32 out
    dim3 g2(Sv / BM, Sv / BN, Bv);
    gemm_nt_tf32<<<g2, THREADS, SMEM_BYTES>>>(Qc, 1024, rowQK, Kc, 1024, rowQK, bias, 1.f, Sc, 512, rowSS, 1024, 0);

    // Stage 3: softmax -> d_out first half (full fp32) + rna copy in Sc
    softmax512<<<(unsigned)M, 128>>>(Sc, out, Sc);

    // Stage 4: output[b] = att_b @ V_b^T -> d_out second half
    gemm_nt_tf32<<<g2, THREADS, SMEM_BYTES>>>(Sc, 512, rowSS, V, 512, rowSS, nullptr, 1.f,
                                              out + (long)Bv * rowSS, 512, rowSS, 512, 0);
}

// round 4
// speedup vs baseline: 1.6819x; 1.5927x over previous
#include <cuda_runtime.h>
#include <cuda_fp16.h>
#include <cstdint>

// ---------------------------------------------------------------------------
// Conversation_Self_Attention: B=64, S=512, D=DK=DV=512  (sm_103 mma.sync;
// tcgen05 unavailable: bench PTX stage targets plain sm_103)
//
// fp16 HMMA path (m16n8k16, fp32 accum). fp16 rna rounding == tf32 rna for
// all in-range values (same 10 mantissa bits) -> numerics match the passing
// tf32 build (rel_err ~4.4e-4).
//
//   Ah/Ph/W* = half(sent/pos/weights)
//   Qc = [ half((sent@Wq^T+bq)*2^-5) | half((pos@Wpq^T+bpq)*2^-5) ] [B*S,1024]
//   Kc = [ half(sent@Wk^T+bk)        | half(pos@Wpk^T+bpk)        ] [B*S,1024]
//   V  =   half(sent@Wv^T+bv)                                       [B*S,512]
//   scores[b] = Qc_b @ Kc_b^T + bias   (fp32)
//   att = softmax(scores) -> d_out[0:B*S*S] fp32  + half copy for stage 4
//   out[b] = att_b @ V_b^T -> d_out[B*S*S:]       fp32
// ---------------------------------------------------------------------------

#define BM 128
#define BN 128
#define BK 32                 // halves per row chunk (64B)
#define BKP 40                // padded row (80B) -> conflict-free LDS
#define NSTAGE 3
#define THREADS 128
#define TILE_H (BM * BKP)                       // halves per operand tile
#define SMEM_BYTES (NSTAGE * 2 * TILE_H * 2)    // 61440

static const int Bv = 64, Sv = 512;

// scratch (static device arrays: allocation-free contract)
__device__ __align__(128) __half g_Ah[64L * 512 * 512];
__device__ __align__(128) __half g_Ph[64L * 512 * 512];
__device__ __align__(128) __half g_Wh[5L * 512 * 512];
__device__ __align__(128) __half g_Qc[64L * 512 * 1024];
__device__ __align__(128) __half g_Kc[64L * 512 * 1024];
__device__ __align__(128) __half g_V [64L * 512 * 512];
__device__ __align__(128) __half g_At[64L * 512 * 512];   // half(att)
__device__ float g_S[64L * 512 * 512];                    // fp32 scores

// ---------------- fp16 NT GEMM: C[z] = (A[z] @ B[z]^T + bias) * alpha -------
// OutT = __half (rna-rounded intermediate) or float.
template <typename OutT>
__global__ void __launch_bounds__(THREADS, 2)
gemm_nt_f16(const __half* __restrict__ A, int lda, long As,
            const __half* __restrict__ B, int ldb, long Bs,
            const float* __restrict__ bias, float alpha,
            OutT* __restrict__ C, int ldc, long Cs,
            int K)
{
    extern __shared__ __half smem[];
    // layout: stage s: A tile at s*2*TILE_H, B tile at s*2*TILE_H + TILE_H

    const int tid  = threadIdx.x;
    const int lane = tid & 31;
    const int warp = tid >> 5;
    const int wm   = warp & 1;            // 2 warps in M -> 64 rows/warp
    const int wn   = warp >> 1;           // 2 warps in N -> 64 cols/warp

    const int bm = blockIdx.x * BM;
    const int bn = blockIdx.y * BN;
    const int z  = blockIdx.z;

    const __half* Ab = A + (size_t)z * As;
    const __half* Bb = B + (size_t)z * Bs;
    OutT*         Cb = C + (size_t)z * Cs;

    const int row4 = tid >> 2;            // 0..31
    const int ch   = tid & 3;             // 16B chunk in 64B row

    float acc[4][8][4];
    #pragma unroll
    for (int i = 0; i < 4; i++)
        #pragma unroll
        for (int j = 0; j < 8; j++)
            #pragma unroll
            for (int k = 0; k < 4; k++) acc[i][j][k] = 0.f;

    auto load_tile = [&](int kt) {
        const int st = kt % NSTAGE;
        __half* dA = smem + st * 2 * TILE_H;
        __half* dB = dA + TILE_H;
        const int k0 = kt * BK;
        #pragma unroll
        for (int i = 0; i < 4; i++) {
            const int row = row4 + i * 32;
            {
                const __half* g = Ab + (size_t)(bm + row) * lda + k0 + ch * 8;
                unsigned s = (unsigned)__cvta_generic_to_shared(dA + row * BKP + ch * 8);
                asm volatile("cp.async.cg.shared.global [%0], [%1], 16;\n" :: "r"(s), "l"(g));
            }
            {
                const __half* g = Bb + (size_t)(bn + row) * ldb + k0 + ch * 8;
                unsigned s = (unsigned)__cvta_generic_to_shared(dB + row * BKP + ch * 8);
                asm volatile("cp.async.cg.shared.global [%0], [%1], 16;\n" :: "r"(s), "l"(g));
            }
        }
        asm volatile("cp.async.commit_group;\n");
    };

    const int KT = K / BK;
    load_tile(0);
    if (KT > 1) load_tile(1);

    for (int kt = 0; kt < KT; kt++) {
        const int st = kt % NSTAGE;
        if (kt + 2 < KT) {
            load_tile(kt + 2);
            asm volatile("cp.async.wait_group 2;\n");
        } else if (kt + 1 < KT) {
            asm volatile("cp.async.wait_group 1;\n");
        } else {
            asm volatile("cp.async.wait_group 0;\n");
        }
        __syncthreads();

        const __half* tA = smem + st * 2 * TILE_H;
        const __half* tB = tA + TILE_H;

        #pragma unroll
        for (int kk = 0; kk < 2; kk++) {
            const int kb = kk * 16;
            unsigned a[4][4], b[8][2];
            const int p2   = (lane & 3) * 2;
            const int arow = wm * 64 + (lane >> 2);
            #pragma unroll
            for (int mt = 0; mt < 4; mt++) {
                const int r = arow + mt * 16;
                a[mt][0] = *(const unsigned*)&tA[(r    ) * BKP + kb + p2    ];
                a[mt][1] = *(const unsigned*)&tA[(r + 8) * BKP + kb + p2    ];
                a[mt][2] = *(const unsigned*)&tA[(r    ) * BKP + kb + p2 + 8];
                a[mt][3] = *(const unsigned*)&tA[(r + 8) * BKP + kb + p2 + 8];
            }
            const int bcol = wn * 64 + (lane >> 2);
            #pragma unroll
            for (int nt = 0; nt < 8; nt++) {
                const int c = bcol + nt * 8;
                b[nt][0] = *(const unsigned*)&tB[c * BKP + kb + p2    ];
                b[nt][1] = *(const unsigned*)&tB[c * BKP + kb + p2 + 8];
            }
            #pragma unroll
            for (int mt = 0; mt < 4; mt++)
                #pragma unroll
                for (int nt = 0; nt < 8; nt++) {
                    float* d = acc[mt][nt];
                    asm volatile(
                        "mma.sync.aligned.m16n8k16.row.col.f32.f16.f16.f32 "
                        "{%0,%1,%2,%3}, {%4,%5,%6,%7}, {%8,%9}, {%0,%1,%2,%3};\n"
                        : "+f"(d[0]), "+f"(d[1]), "+f"(d[2]), "+f"(d[3])
                        : "r"(a[mt][0]), "r"(a[mt][1]), "r"(a[mt][2]), "r"(a[mt][3]),
                          "r"(b[nt][0]), "r"(b[nt][1]));
                }
        }
        __syncthreads();
    }

    #pragma unroll
    for (int mt = 0; mt < 4; mt++) {
        const int row = bm + wm * 64 + mt * 16 + (lane >> 2);
        #pragma unroll
        for (int nt = 0; nt < 8; nt++) {
            const int col = bn + wn * 64 + nt * 8 + (lane & 3) * 2;
            float b0 = 0.f, b1 = 0.f;
            if (bias) { b0 = bias[col]; b1 = bias[col + 1]; }
            const float* d = acc[mt][nt];
            const float v0 = (d[0] + b0) * alpha;
            const float v1 = (d[1] + b1) * alpha;
            const float v2 = (d[2] + b0) * alpha;
            const float v3 = (d[3] + b1) * alpha;
            if constexpr (sizeof(OutT) == 2) {
                *reinterpret_cast<__half2*>((__half*)Cb + (size_t)(row    ) * ldc + col) =
                    __floats2half2_rn(v0, v1);
                *reinterpret_cast<__half2*>((__half*)Cb + (size_t)(row + 8) * ldc + col) =
                    __floats2half2_rn(v2, v3);
            } else {
                *reinterpret_cast<float2*>((float*)Cb + (size_t)(row    ) * ldc + col) =
                    make_float2(v0, v1);
                *reinterpret_cast<float2*>((float*)Cb + (size_t)(row + 8) * ldc + col) =
                    make_float2(v2, v3);
            }
        }
    }
}

// ---------------- fp32 -> fp16 (rna) bulk convert ----------------
__global__ void to_half(const float* __restrict__ x, __half* __restrict__ y, long n)
{
    long i = ((long)blockIdx.x * blockDim.x + threadIdx.x) * 8;
    if (i >= n) return;
    const float4 v0 = *reinterpret_cast<const float4*>(x + i);
    const float4 v1 = *reinterpret_cast<const float4*>(x + i + 4);
    __half2 h[4];
    h[0] = __floats2half2_rn(v0.x, v0.y);
    h[1] = __floats2half2_rn(v0.z, v0.w);
    h[2] = __floats2half2_rn(v1.x, v1.y);
    h[3] = __floats2half2_rn(v1.z, v1.w);
    *reinterpret_cast<uint4*>(y + i) = *reinterpret_cast<const uint4*>(h);
}

// ---------------- softmax over 512: fp32 out + fp16 copy ----------------
__global__ void softmax512(const float* __restrict__ S,
                           float* __restrict__ Ofull,
                           __half* __restrict__ Oh)
{
    const long row = blockIdx.x;
    const int tid = threadIdx.x;
    const float4 v = ((const float4*)(S + row * 512))[tid];

    float m = fmaxf(fmaxf(v.x, v.y), fmaxf(v.z, v.w));
    #pragma unroll
    for (int off = 16; off; off >>= 1) m = fmaxf(m, __shfl_xor_sync(~0u, m, off));
    __shared__ float redm[4];
    if ((tid & 31) == 0) redm[tid >> 5] = m;
    __syncthreads();
    m = fmaxf(fmaxf(redm[0], redm[1]), fmaxf(redm[2], redm[3]));

    const float e0 = __expf(v.x - m), e1 = __expf(v.y - m);
    const float e2 = __expf(v.z - m), e3 = __expf(v.w - m);
    float s = e0 + e1 + e2 + e3;
    #pragma unroll
    for (int off = 16; off; off >>= 1) s += __shfl_xor_sync(~0u, s, off);
    __shared__ float reds[4];
    if ((tid & 31) == 0) reds[tid >> 5] = s;
    __syncthreads();
    s = reds[0] + reds[1] + reds[2] + reds[3];

    const float inv = 1.0f / s;
    const float p0 = e0 * inv, p1 = e1 * inv, p2 = e2 * inv, p3 = e3 * inv;
    ((float4*)(Ofull + row * 512))[tid] = make_float4(p0, p1, p2, p3);
    __half2 h[2] = { __floats2half2_rn(p0, p1), __floats2half2_rn(p2, p3) };
    ((uint2*)(Oh + row * 512))[tid] = *reinterpret_cast<const uint2*>(h);
}

// ---------------- launcher ----------------
extern "C" void kernel_launch(void* const* d_in, const int* in_sizes, int n_in,
                              void* d_out, int out_size)
{
    const float* sent = (const float*)d_in[0];
    const float* pos  = (const float*)d_in[1];
    // d_in[2] = branch_emb: unused by the reference
    const float* Wq   = (const float*)d_in[3];
    const float* bq   = (const float*)d_in[4];
    const float* Wk   = (const float*)d_in[5];
    const float* bk   = (const float*)d_in[6];
    const float* Wv   = (const float*)d_in[7];
    const float* bv   = (const float*)d_in[8];
    const float* Wpq  = (const float*)d_in[9];
    const float* bpq  = (const float*)d_in[10];
    const float* Wpk  = (const float*)d_in[11];
    const float* bpk  = (const float*)d_in[12];
    const float* bias = (const float*)d_in[13];
    float* out = (float*)d_out;

    __half *Ah, *Ph, *Wh, *Qc, *Kc, *V, *At;
    float *Sc;
    cudaGetSymbolAddress((void**)&Ah, g_Ah);
    cudaGetSymbolAddress((void**)&Ph, g_Ph);
    cudaGetSymbolAddress((void**)&Wh, g_Wh);
    cudaGetSymbolAddress((void**)&Qc, g_Qc);
    cudaGetSymbolAddress((void**)&Kc, g_Kc);
    cudaGetSymbolAddress((void**)&V,  g_V);
    cudaGetSymbolAddress((void**)&At, g_At);
    cudaGetSymbolAddress((void**)&Sc, g_S);

    cudaFuncSetAttribute(gemm_nt_f16<__half>, cudaFuncAttributeMaxDynamicSharedMemorySize, SMEM_BYTES);
    cudaFuncSetAttribute(gemm_nt_f16<float>,  cudaFuncAttributeMaxDynamicSharedMemorySize, SMEM_BYTES);

    const long nEmb = (long)Bv * Sv * 512;      // 16,777,216
    const long nW   = 512L * 512;               // 262,144
    const float norm = 0.03125f;                // 1/sqrt(2*512), exact pow2
    const long  M     = (long)Bv * Sv;          // 32768
    const long  rowQK = 512L * 1024;
    const long  rowSS = 512L * 512;

    // Stage 0: rna-convert all GEMM operands to fp16
    to_half<<<(unsigned)(nEmb / 4096), 512>>>(sent, Ah, nEmb);
    to_half<<<(unsigned)(nEmb / 4096), 512>>>(pos,  Ph, nEmb);
    to_half<<<(unsigned)(nW / 4096), 512>>>(Wq,  Wh + 0 * nW, nW);
    to_half<<<(unsigned)(nW / 4096), 512>>>(Wk,  Wh + 1 * nW, nW);
    to_half<<<(unsigned)(nW / 4096), 512>>>(Wv,  Wh + 2 * nW, nW);
    to_half<<<(unsigned)(nW / 4096), 512>>>(Wpq, Wh + 3 * nW, nW);
    to_half<<<(unsigned)(nW / 4096), 512>>>(Wpk, Wh + 4 * nW, nW);

    // Stage 1: projections (M=32768, N=512, K=512) -> fp16 intermediates
    dim3 g1((unsigned)(M / BM), 512 / BN, 1);
    gemm_nt_f16<__half><<<g1, THREADS, SMEM_BYTES>>>(Ah, 512, 0, Wh + 0 * nW, 512, 0, bq,  norm, Qc,       1024, 0, 512);
    gemm_nt_f16<__half><<<g1, THREADS, SMEM_BYTES>>>(Ph, 512, 0, Wh + 3 * nW, 512, 0, bpq, norm, Qc + 512, 1024, 0, 512);
    gemm_nt_f16<__half><<<g1, THREADS, SMEM_BYTES>>>(Ah, 512, 0, Wh + 1 * nW, 512, 0, bk,  1.f,  Kc,       1024, 0, 512);
    gemm_nt_f16<__half><<<g1, THREADS, SMEM_BYTES>>>(Ph, 512, 0, Wh + 4 * nW, 512, 0, bpk, 1.f,  Kc + 512, 1024, 0, 512);
    gemm_nt_f16<__half><<<g1, THREADS, SMEM_BYTES>>>(Ah, 512, 0, Wh + 2 * nW, 512, 0, bv,  1.f,  V,         512, 0, 512);

    // Stage 2: fused text+pos scores per batch (K=1024) + bias -> fp32
    dim3 g2(Sv / BM, Sv / BN, Bv);
    gemm_nt_f16<float><<<g2, THREADS, SMEM_BYTES>>>(Qc, 1024, rowQK, Kc, 1024, rowQK, bias, 1.f, Sc, 512, rowSS, 1024);

    // Stage 3: softmax -> d_out first half (fp32) + fp16 att for stage 4
    softmax512<<<(unsigned)M, 128>>>(Sc, out, At);

    // Stage 4: output[b] = att_b @ V_b^T -> d_out second half
    gemm_nt_f16<float><<<g2, THREADS, SMEM_BYTES>>>(At, 512, rowSS, V, 512, rowSS, nullptr, 1.f,
                                                    out + (long)Bv * rowSS, 512, rowSS, 512);
}